// round 16
// baseline (speedup 1.0000x reference)
#include <cuda_runtime.h>
#include <cuda_fp16.h>
#include <cstdint>

#define DEV_INLINE __device__ __forceinline__

static constexpr int NDIM   = 1024;
static constexpr int NBATCH = 32;

// GEMM tiling (portable mma.sync; tcgen05 rejected by compute_103 PTX target)
static constexpr int BM = 128;
static constexpr int BN = 128;
static constexpr int BK = 64;
static constexpr int STAGES = 3;
static constexpr int THREADS = 256;   // 8 warps: 2(m) x 4(n), warp tile 64x32 (proven)

static constexpr int A_STAGE_BYTES = BM * 128;              // 16 KB
static constexpr int B_STAGE_BYTES = BK * 256;              // 16 KB
static constexpr int STAGE_BYTES   = A_STAGE_BYTES + B_STAGE_BYTES;   // 32 KB
static constexpr int SMEM_TOTAL    = STAGES * STAGE_BYTES;  // 96 KB

// Folded DCT (level 2 on even branch), B operands in INPUT layout [b][j][m]:
//   odd rows k=2r+1: Out = Codd(512x512) @ d    d[j]  = x[j]-x[1023-j]
//   rows k=4t:       Out = Cee (256x256) @ ss   ss[j] = s[j]+s[511-j]
//   rows k=4t+2:     Out = Ceo (256x256) @ sd   sd[j] = s[j]-s[511-j],  s[j]=x[j]+x[1023-j]
__device__ __half d_Codd[512 * 512];                    // [r][j] K-contig
__device__ __half d_Cee[256 * 256];
__device__ __half d_Ceo[256 * 256];
__device__ __half d_xd [(size_t)NBATCH * 512 * 1024];   // [b][j<512][m]
__device__ __half d_xss[(size_t)NBATCH * 256 * 1024];   // [b][j<256][m]
__device__ __half d_xsd[(size_t)NBATCH * 256 * 1024];

// ---------------------------------------------------------------- helpers
DEV_INLINE uint32_t smem_u32(const void* p) {
    uint32_t a;
    asm("{ .reg .u64 t; cvta.to.shared.u64 t, %1; cvt.u32.u64 %0, t; }" : "=r"(a) : "l"(p));
    return a;
}
DEV_INLINE void cp16(uint32_t saddr, const void* g) {
    asm volatile("cp.async.cg.shared.global [%0], [%1], 16;" :: "r"(saddr), "l"(g));
}
DEV_INLINE void cp_commit() { asm volatile("cp.async.commit_group;"); }
template <int N> DEV_INLINE void cp_wait() { asm volatile("cp.async.wait_group %0;" :: "n"(N)); }
DEV_INLINE uint32_t swz(uint32_t off) { return off ^ ((off >> 3) & 0x70); }

DEV_INLINE void ldsm4(uint32_t* r, uint32_t addr) {
    asm volatile("ldmatrix.sync.aligned.m8n8.x4.shared.b16 {%0,%1,%2,%3}, [%4];"
                 : "=r"(r[0]), "=r"(r[1]), "=r"(r[2]), "=r"(r[3]) : "r"(addr));
}
DEV_INLINE void ldsm4t(uint32_t* r, uint32_t addr) {
    asm volatile("ldmatrix.sync.aligned.m8n8.x4.trans.shared.b16 {%0,%1,%2,%3}, [%4];"
                 : "=r"(r[0]), "=r"(r[1]), "=r"(r[2]), "=r"(r[3]) : "r"(addr));
}
DEV_INLINE void mma16816(float* c, const uint32_t* a, const uint32_t* b) {
    asm volatile(
        "mma.sync.aligned.m16n8k16.row.col.f32.f16.f16.f32 "
        "{%0,%1,%2,%3}, {%4,%5,%6,%7}, {%8,%9}, {%0,%1,%2,%3};"
        : "+f"(c[0]), "+f"(c[1]), "+f"(c[2]), "+f"(c[3])
        : "r"(a[0]), "r"(a[1]), "r"(a[2]), "r"(a[3]), "r"(b[0]), "r"(b[1]));
}
DEV_INLINE uint32_t f2h2(float a, float b) {
    __half2 h = __floats2half2_rn(a, b);
    return *reinterpret_cast<uint32_t*>(&h);
}
DEV_INLINE float4 add4(float4 a, float4 b) { return {a.x+b.x, a.y+b.y, a.z+b.z, a.w+b.w}; }
DEV_INLINE float4 sub4(float4 a, float4 b) { return {a.x-b.x, a.y-b.y, a.z-b.z, a.w-b.w}; }
DEV_INLINE void st8h(__half* p, float4 u, float4 v) {
    uint4 o = { f2h2(u.x,u.y), f2h2(u.z,u.w), f2h2(v.x,v.y), f2h2(v.z,v.w) };
    *reinterpret_cast<uint4*>(p) = o;
}

// ---------------------------------------------------------------- kernel 1: prep (fold + matrices)
// blocks [0,4096): streaming fold (HBM-roofline).  blocks [4096,5632): matrix build.
__global__ void prep_kernel(const float* __restrict__ x) {
    int blk = blockIdx.x;
    if (blk < 4096) {
        int idx = blk * 256 + threadIdx.x;          // 0 .. 1048575
        int b = idx >> 15;
        int rem = idx & 32767;
        int j = rem >> 7;                            // 0..255
        int m = (rem & 127) << 3;                    // 8 floats
        const float* xb = x + ((size_t)b << 20);
        const float4* pa = (const float4*)(xb + (size_t)j * 1024 + m);
        const float4* pb = (const float4*)(xb + (size_t)(1023 - j) * 1024 + m);
        const float4* pc = (const float4*)(xb + (size_t)(511 - j) * 1024 + m);
        const float4* pe = (const float4*)(xb + (size_t)(512 + j) * 1024 + m);
        float4 a0 = pa[0], a1 = pa[1];
        float4 b0 = pb[0], b1 = pb[1];
        float4 c0 = pc[0], c1 = pc[1];
        float4 e0 = pe[0], e1 = pe[1];
        float4 slo0 = add4(a0, b0), slo1 = add4(a1, b1);   // s[j]
        float4 shi0 = add4(c0, e0), shi1 = add4(c1, e1);   // s[511-j]
        st8h(d_xd  + ((size_t)b * 512 + j)       * 1024 + m, sub4(a0, b0), sub4(a1, b1));
        st8h(d_xd  + ((size_t)b * 512 + 511 - j) * 1024 + m, sub4(c0, e0), sub4(c1, e1));
        st8h(d_xss + ((size_t)b * 256 + j)       * 1024 + m, add4(slo0, shi0), add4(slo1, shi1));
        st8h(d_xsd + ((size_t)b * 256 + j)       * 1024 + m, sub4(slo0, shi0), sub4(slo1, shi1));
    } else {
        int idx = (blk - 4096) * 256 + threadIdx.x;  // 0 .. 393215
        int k, j;
        __half* dst;
        if (idx < 262144) {                          // Codd
            j = idx & 511; k = 2 * (idx >> 9) + 1; dst = d_Codd + idx;
        } else if (idx < 327680) {                   // Cee
            int l = idx - 262144;
            j = l & 255; k = 4 * (l >> 8); dst = d_Cee + l;
        } else {                                     // Ceo
            int l = idx - 327680;
            j = l & 255; k = 4 * (l >> 8) + 2; dst = d_Ceo + l;
        }
        int t = ((k * (2 * j + 1) + 2048) & 4095) - 2048;
        float ang = (float)t * 1.5339807878856412e-3f;   // pi/2048
        float s = (k == 0) ? 0.03125f : 0.04419417382415922f;
        *dst = __float2half(s * __cosf(ang));
    }
}

// ---------------------------------------------------------------- GEMM machinery (proven)
// One chunk load: A tile 128 rows x 64 k (stride KD), B tile 64 k-rows x 128 m (trans layout)
template <int KD>
DEV_INLINE void load_chunkT(int kc0, int stage, int tid, const __half* Asrc,
                            const __half* Bsrc, uint32_t sbase) {
    uint32_t abase = sbase + stage * STAGE_BYTES;
    uint32_t bbase = abase + A_STAGE_BYTES;
#pragma unroll
    for (int i = 0; i < 4; i++) {
        int s = tid + i * THREADS;
        int row = s >> 3, seg = s & 7;
        cp16(abase + swz((uint32_t)(row * 128 + seg * 16)),
             (const void*)(Asrc + (size_t)row * KD + kc0 + seg * 8));
    }
#pragma unroll
    for (int i = 0; i < 4; i++) {
        int s = tid + i * THREADS;
        int krow = s >> 4, seg = s & 15;
        cp16(bbase + (uint32_t)((seg >> 3) * 8192) +
                 swz((uint32_t)(krow * 128 + (seg & 7) * 16)),
             (const void*)(Bsrc + (size_t)(kc0 + krow) * 1024 + seg * 8));
    }
}

// MMA block for one resident chunk (stage index st)
#define MMA_CHUNK(st)                                                              \
    do {                                                                           \
        uint32_t abase_ = sbase + (st) * STAGE_BYTES;                              \
        uint32_t bbase_ = abase_ + A_STAGE_BYTES;                                  \
        _Pragma("unroll")                                                          \
        for (int ks = 0; ks < 4; ks++) {                                           \
            uint32_t af[4][4];                                                     \
            _Pragma("unroll")                                                      \
            for (int mi = 0; mi < 4; mi++)                                         \
                ldsm4(af[mi], abase_ + swz((uint32_t)((a_row + mi * 16) * 128 +    \
                                                      (ks * 16 + a_kx) * 2)));     \
            uint32_t bf[4][2];                                                     \
            _Pragma("unroll")                                                      \
            for (int h = 0; h < 2; h++) {                                          \
                int nb = warp_n * 32 + h * 16 + b_ns;                              \
                uint32_t r[4];                                                     \
                ldsm4t(r, bbase_ + (uint32_t)(((nb >> 6) & 1) * 8192) +            \
                          swz((uint32_t)((ks * 16 + b_jr) * 128 + (nb & 63) * 2)));\
                bf[2 * h + 0][0] = r[0]; bf[2 * h + 0][1] = r[1];                  \
                bf[2 * h + 1][0] = r[2]; bf[2 * h + 1][1] = r[3];                  \
            }                                                                      \
            _Pragma("unroll")                                                      \
            for (int mi = 0; mi < 4; mi++)                                         \
                _Pragma("unroll")                                                  \
                for (int ni = 0; ni < 4; ni++)                                     \
                    mma16816(acc[mi][ni], af[mi], bf[ni]);                         \
        }                                                                          \
    } while (0)

// 512-path: odd rows, 3-stage pipelined K=512 (proven)
DEV_INLINE void gemm512_body(float* __restrict__ out, int blk, uint32_t sbase, char* smem) {
    int tid = threadIdx.x;
    int lane = tid & 31, wid = tid >> 5;
    int warp_m = wid & 1;
    int warp_n = wid >> 1;

    int k0 = (blk & 3) * BM;
    int nt = blk >> 2;
    int b  = nt >> 3;
    int m0 = (nt & 7) * BN;
    const __half* Apanel = d_Codd + (size_t)k0 * 512;
    const __half* Bpanel = d_xd + (size_t)b * 512 * 1024 + m0;

    float acc[4][4][4] = {};

    int a_row = warp_m * 64 + (lane & 7) + (((lane >> 3) & 1) << 3);
    int a_kx  = (lane >> 4) << 3;
    int b_jr  = (lane & 7) + (((lane >> 3) & 1) << 3);
    int b_ns  = (lane >> 4) << 3;

    load_chunkT<512>(0, 0, tid, Apanel, Bpanel, sbase); cp_commit();
    load_chunkT<512>(64, 1, tid, Apanel, Bpanel, sbase); cp_commit();

    for (int c = 0; c < 8; c++) {
        int q = c + 2;
        if (q < 8) load_chunkT<512>(q * 64, q % 3, tid, Apanel, Bpanel, sbase);
        cp_commit();
        cp_wait<2>();
        __syncthreads();

        MMA_CHUNK(c % 3);
        __syncthreads();
    }

    // epilogue: smem staging -> float4 stores, output rows 2*(k0+rr)+1
    float* stg = (float*)smem;
    int gr = lane >> 2, cl = (lane & 3) * 2;
#pragma unroll
    for (int mi = 0; mi < 4; mi++)
#pragma unroll
        for (int ni = 0; ni < 4; ni++) {
            int r0 = warp_m * 64 + mi * 16 + gr;
            int col = warp_n * 32 + ni * 8 + cl;
            stg[r0 * 132 + col]           = acc[mi][ni][0];
            stg[r0 * 132 + col + 1]       = acc[mi][ni][1];
            stg[(r0 + 8) * 132 + col]     = acc[mi][ni][2];
            stg[(r0 + 8) * 132 + col + 1] = acc[mi][ni][3];
        }
    __syncthreads();

    size_t ob = ((size_t)b << 20) + (size_t)(2 * k0 + 1) * 1024 + m0;
#pragma unroll
    for (int i = 0; i < 16; i++) {
        int idx = i * THREADS + tid;
        int row = idx >> 5;
        int c4 = (idx & 31) * 4;
        float4 v = *(const float4*)(stg + row * 132 + c4);
        *(float4*)(out + ob + (size_t)row * 2048 + c4) = v;
    }
}

// Paired 256-path: one CTA does the (ee, kt) AND (eo, kt) tiles of one n-tile
// through the SAME 8-chunk 3-stage pipeline (pointer swap at chunk 4), with a
// direct-store epilogue (R13-proven mapping) after chunks 3 and 7.
DEV_INLINE void gemm256x2_body(float* __restrict__ out, int blk, uint32_t sbase) {
    int tid = threadIdx.x;
    int lane = tid & 31, wid = tid >> 5;
    int warp_m = wid & 1;
    int warp_n = wid >> 1;

    int kt = blk & 1;                   // k-tile within the 256-row matrices
    int nt = blk >> 1;
    int b  = nt >> 3;
    int m0 = (nt & 7) * BN;
    const __half* Aee = d_Cee + (size_t)(kt * 128) * 256;
    const __half* Aeo = d_Ceo + (size_t)(kt * 128) * 256;
    const __half* Bss = d_xss + (size_t)b * 256 * 1024 + m0;
    const __half* Bsd = d_xsd + (size_t)b * 256 * 1024 + m0;

    float acc[4][4][4] = {};

    int a_row = warp_m * 64 + (lane & 7) + (((lane >> 3) & 1) << 3);
    int a_kx  = (lane >> 4) << 3;
    int b_jr  = (lane & 7) + (((lane >> 3) & 1) << 3);
    int b_ns  = (lane >> 4) << 3;
    int gr = lane >> 2, cl = (lane & 3) * 2;

    load_chunkT<256>(0, 0, tid, Aee, Bss, sbase); cp_commit();
    load_chunkT<256>(64, 1, tid, Aee, Bss, sbase); cp_commit();

    for (int c = 0; c < 8; c++) {
        int q = c + 2;
        if (q < 8) {
            const __half* Aq = (q < 4) ? Aee : Aeo;
            const __half* Bq = (q < 4) ? Bss : Bsd;
            load_chunkT<256>((q & 3) * 64, q % 3, tid, Aq, Bq, sbase);
        }
        cp_commit();
        cp_wait<2>();
        __syncthreads();

        MMA_CHUNK(c % 3);

        if (c == 3 || c == 7) {
            // direct epilogue: ee -> rows 4*r0, eo -> rows 4*r0+2  (r0 = kt*128 + rr)
            int rowoff = (c == 3) ? 0 : 2;
            size_t obase = ((size_t)b << 20) + (size_t)rowoff * 1024 + m0;
#pragma unroll
            for (int mi = 0; mi < 4; mi++)
#pragma unroll
                for (int ni = 0; ni < 4; ni++) {
                    int r0 = kt * 128 + warp_m * 64 + mi * 16 + gr;
                    int col = warp_n * 32 + ni * 8 + cl;
                    float2 v0 = { acc[mi][ni][0], acc[mi][ni][1] };
                    float2 v1 = { acc[mi][ni][2], acc[mi][ni][3] };
                    *(float2*)(out + obase + (size_t)(4 * r0) * 1024 + col)       = v0;
                    *(float2*)(out + obase + (size_t)(4 * (r0 + 8)) * 1024 + col) = v1;
                    acc[mi][ni][0] = acc[mi][ni][1] = 0.0f;
                    acc[mi][ni][2] = acc[mi][ni][3] = 0.0f;
                }
        }
        __syncthreads();
    }
}

// One launch, 1536 structurally identical 8-chunk CTAs:
//   [0,1024):    odd rows, K=512
//   [1024,1536): paired ee+eo, 2 x K=256
__global__ void __launch_bounds__(THREADS, 2) fused_gemm_kernel(float* __restrict__ out) {
    extern __shared__ char smem[];
    uint32_t sbase = smem_u32(smem);
    int blk = blockIdx.x;
    if (blk < 1024) gemm512_body(out, blk, sbase, smem);
    else            gemm256x2_body(out, blk - 1024, sbase);
}

// ---------------------------------------------------------------- launch
extern "C" void kernel_launch(void* const* d_in, const int* in_sizes, int n_in,
                              void* d_out, int out_size) {
    (void)in_sizes; (void)n_in; (void)out_size;
    const float* x = (const float*)d_in[0];
    float* out = (float*)d_out;

    prep_kernel<<<5632, 256>>>(x);

    cudaFuncSetAttribute(fused_gemm_kernel,
                         cudaFuncAttributeMaxDynamicSharedMemorySize, SMEM_TOTAL);
    fused_gemm_kernel<<<1536, THREADS, SMEM_TOTAL>>>(out);
}

// round 17
// speedup vs baseline: 1.0365x; 1.0365x over previous
#include <cuda_runtime.h>
#include <cuda_fp16.h>
#include <cstdint>

#define DEV_INLINE __device__ __forceinline__

static constexpr int NBATCH = 32;

// GEMM tiling (portable mma.sync; tcgen05 rejected by compute_103 PTX target)
static constexpr int BM = 128;
static constexpr int BN = 128;
static constexpr int BK = 64;
static constexpr int THREADS = 256;   // 8 warps: 2(m) x 4(n), warp tile 64x32 (proven)

static constexpr int A_STAGE_BYTES = BM * 128;              // 16 KB
static constexpr int B_STAGE_BYTES = BK * 256;              // 16 KB
static constexpr int STAGE_BYTES   = A_STAGE_BYTES + B_STAGE_BYTES;   // 32 KB
static constexpr int SMEM_TOTAL    = 3 * STAGE_BYTES;       // 96 KB

// Folded DCT, level 3 on the even-even branch. B operands in INPUT layout [b][j][m]:
//   rows 2r+1: Codd(512x512) @ d     d[j]  = x[j]-x[1023-j]                (j<512)
//   rows 4t+2: Ceo (256x256) @ sd    sd[j] = s[j]-s[511-j]                 (j<256)
//   rows 8u:   Cee2(128x128) @ ss2   ss2[j]= ss[j]+ss[255-j]               (j<128)
//   rows 8u+4: Ceo2(128x128) @ sd2   sd2[j]= ss[j]-ss[255-j]
//   with s[j] = x[j]+x[1023-j],  ss[j] = s[j]+s[511-j]
__device__ __half d_Codd[512 * 512];                    // [r][j] K-contig
__device__ __half d_Ceo [256 * 256];
__device__ __half d_Cee2[128 * 128];
__device__ __half d_Ceo2[128 * 128];
__device__ __half d_xd  [(size_t)NBATCH * 512 * 1024];  // [b][j<512][m]
__device__ __half d_xsd [(size_t)NBATCH * 256 * 1024];  // [b][j<256][m]
__device__ __half d_xss2[(size_t)NBATCH * 128 * 1024];  // [b][j<128][m]
__device__ __half d_xsd2[(size_t)NBATCH * 128 * 1024];

// ---------------------------------------------------------------- helpers
DEV_INLINE uint32_t smem_u32(const void* p) {
    uint32_t a;
    asm("{ .reg .u64 t; cvta.to.shared.u64 t, %1; cvt.u32.u64 %0, t; }" : "=r"(a) : "l"(p));
    return a;
}
DEV_INLINE void cp16(uint32_t saddr, const void* g) {
    asm volatile("cp.async.cg.shared.global [%0], [%1], 16;" :: "r"(saddr), "l"(g));
}
DEV_INLINE void cp_commit() { asm volatile("cp.async.commit_group;"); }
template <int N> DEV_INLINE void cp_wait() { asm volatile("cp.async.wait_group %0;" :: "n"(N)); }
DEV_INLINE uint32_t swz(uint32_t off) { return off ^ ((off >> 3) & 0x70); }

DEV_INLINE void ldsm4(uint32_t* r, uint32_t addr) {
    asm volatile("ldmatrix.sync.aligned.m8n8.x4.shared.b16 {%0,%1,%2,%3}, [%4];"
                 : "=r"(r[0]), "=r"(r[1]), "=r"(r[2]), "=r"(r[3]) : "r"(addr));
}
DEV_INLINE void ldsm4t(uint32_t* r, uint32_t addr) {
    asm volatile("ldmatrix.sync.aligned.m8n8.x4.trans.shared.b16 {%0,%1,%2,%3}, [%4];"
                 : "=r"(r[0]), "=r"(r[1]), "=r"(r[2]), "=r"(r[3]) : "r"(addr));
}
DEV_INLINE void mma16816(float* c, const uint32_t* a, const uint32_t* b) {
    asm volatile(
        "mma.sync.aligned.m16n8k16.row.col.f32.f16.f16.f32 "
        "{%0,%1,%2,%3}, {%4,%5,%6,%7}, {%8,%9}, {%0,%1,%2,%3};"
        : "+f"(c[0]), "+f"(c[1]), "+f"(c[2]), "+f"(c[3])
        : "r"(a[0]), "r"(a[1]), "r"(a[2]), "r"(a[3]), "r"(b[0]), "r"(b[1]));
}
DEV_INLINE uint32_t f2h2(float a, float b) {
    __half2 h = __floats2half2_rn(a, b);
    return *reinterpret_cast<uint32_t*>(&h);
}
DEV_INLINE float4 add4(float4 a, float4 b) { return {a.x+b.x, a.y+b.y, a.z+b.z, a.w+b.w}; }
DEV_INLINE float4 sub4(float4 a, float4 b) { return {a.x-b.x, a.y-b.y, a.z-b.z, a.w-b.w}; }
DEV_INLINE void st8h(__half* p, float4 u, float4 v) {
    uint4 o = { f2h2(u.x,u.y), f2h2(u.z,u.w), f2h2(v.x,v.y), f2h2(v.z,v.w) };
    *reinterpret_cast<uint4*>(p) = o;
}

// ---------------------------------------------------------------- kernel 1: prep
// blocks [0,2048): level-3 streaming fold.  blocks [2048,3456): matrix build.
__global__ void prep_kernel(const float* __restrict__ x) {
    int blk = blockIdx.x;
    if (blk < 2048) {
        int idx = blk * 256 + threadIdx.x;          // 0 .. 524287
        int b = idx >> 14;
        int rem = idx & 16383;
        int j = rem >> 7;                            // 0..127
        int m = (rem & 127) << 3;                    // 8 floats
        const float* xb = x + ((size_t)b << 20);
        const float4* pA = (const float4*)(xb + (size_t)j * 1024 + m);          // x[j]
        const float4* pH = (const float4*)(xb + (size_t)(1023 - j) * 1024 + m); // x[1023-j]
        const float4* pP = (const float4*)(xb + (size_t)(255 - j) * 1024 + m);  // x[255-j]
        const float4* pQ = (const float4*)(xb + (size_t)(768 + j) * 1024 + m);  // x[768+j]
        const float4* pR = (const float4*)(xb + (size_t)(256 + j) * 1024 + m);  // x[256+j]
        const float4* pT = (const float4*)(xb + (size_t)(767 - j) * 1024 + m);  // x[767-j]
        const float4* pU = (const float4*)(xb + (size_t)(511 - j) * 1024 + m);  // x[511-j]
        const float4* pV = (const float4*)(xb + (size_t)(512 + j) * 1024 + m);  // x[512+j]
        float4 A0 = pA[0], A1 = pA[1], H0 = pH[0], H1 = pH[1];
        float4 P0 = pP[0], P1 = pP[1], Q0 = pQ[0], Q1 = pQ[1];
        float4 R0 = pR[0], R1 = pR[1], T0 = pT[0], T1 = pT[1];
        float4 U0 = pU[0], U1 = pU[1], V0 = pV[0], V1 = pV[1];

        // odd-branch diffs (4 rows cover [0,512))
        st8h(d_xd + ((size_t)b * 512 + j)       * 1024 + m, sub4(A0, H0), sub4(A1, H1));
        st8h(d_xd + ((size_t)b * 512 + 255 - j) * 1024 + m, sub4(P0, Q0), sub4(P1, Q1));
        st8h(d_xd + ((size_t)b * 512 + 256 + j) * 1024 + m, sub4(R0, T0), sub4(R1, T1));
        st8h(d_xd + ((size_t)b * 512 + 511 - j) * 1024 + m, sub4(U0, V0), sub4(U1, V1));

        // s[j], s[255-j], s[256+j], s[511-j]
        float4 s00 = add4(A0, H0), s01 = add4(A1, H1);
        float4 s10 = add4(P0, Q0), s11 = add4(P1, Q1);
        float4 s20 = add4(R0, T0), s21 = add4(R1, T1);
        float4 s30 = add4(U0, V0), s31 = add4(U1, V1);

        // sd[j] = s[j]-s[511-j];  sd[255-j] = s[255-j]-s[256+j]
        st8h(d_xsd + ((size_t)b * 256 + j)       * 1024 + m, sub4(s00, s30), sub4(s01, s31));
        st8h(d_xsd + ((size_t)b * 256 + 255 - j) * 1024 + m, sub4(s10, s20), sub4(s11, s21));

        // ss[j] = s[j]+s[511-j];  ss[255-j] = s[255-j]+s[256+j]
        float4 ssj0 = add4(s00, s30), ssj1 = add4(s01, s31);
        float4 ssr0 = add4(s10, s20), ssr1 = add4(s11, s21);

        // ss2[j] = ss[j]+ss[255-j];  sd2[j] = ss[j]-ss[255-j]
        st8h(d_xss2 + ((size_t)b * 128 + j) * 1024 + m, add4(ssj0, ssr0), add4(ssj1, ssr1));
        st8h(d_xsd2 + ((size_t)b * 128 + j) * 1024 + m, sub4(ssj0, ssr0), sub4(ssj1, ssr1));
    } else {
        int idx = (blk - 2048) * 256 + threadIdx.x;  // 0 .. 360447
        int k, j;
        __half* dst;
        if (idx < 262144) {                          // Codd: r<512, j<512, k=2r+1
            j = idx & 511; k = 2 * (idx >> 9) + 1; dst = d_Codd + idx;
        } else if (idx < 327680) {                   // Ceo: t<256, j<256, k=4t+2
            int l = idx - 262144;
            j = l & 255; k = 4 * (l >> 8) + 2; dst = d_Ceo + l;
        } else if (idx < 344064) {                   // Cee2: u<128, j<128, k=8u
            int l = idx - 327680;
            j = l & 127; k = 8 * (l >> 7); dst = d_Cee2 + l;
        } else {                                     // Ceo2: k=8u+4
            int l = idx - 344064;
            j = l & 127; k = 8 * (l >> 7) + 4; dst = d_Ceo2 + l;
        }
        int t = ((k * (2 * j + 1) + 2048) & 4095) - 2048;
        float ang = (float)t * 1.5339807878856412e-3f;   // pi/2048
        float s = (k == 0) ? 0.03125f : 0.04419417382415922f;
        *dst = __float2half(s * __cosf(ang));
    }
}

// ---------------------------------------------------------------- GEMM machinery (proven)
template <int KD>
DEV_INLINE void load_chunkT(int kc0, int stage, int tid, const __half* Asrc,
                            const __half* Bsrc, uint32_t sbase) {
    uint32_t abase = sbase + stage * STAGE_BYTES;
    uint32_t bbase = abase + A_STAGE_BYTES;
#pragma unroll
    for (int i = 0; i < 4; i++) {
        int s = tid + i * THREADS;
        int row = s >> 3, seg = s & 7;
        cp16(abase + swz((uint32_t)(row * 128 + seg * 16)),
             (const void*)(Asrc + (size_t)row * KD + kc0 + seg * 8));
    }
#pragma unroll
    for (int i = 0; i < 4; i++) {
        int s = tid + i * THREADS;
        int krow = s >> 4, seg = s & 15;
        cp16(bbase + (uint32_t)((seg >> 3) * 8192) +
                 swz((uint32_t)(krow * 128 + (seg & 7) * 16)),
             (const void*)(Bsrc + (size_t)(kc0 + krow) * 1024 + seg * 8));
    }
}

#define MMA_CHUNK(st)                                                              \
    do {                                                                           \
        uint32_t abase_ = sbase + (st) * STAGE_BYTES;                              \
        uint32_t bbase_ = abase_ + A_STAGE_BYTES;                                  \
        _Pragma("unroll")                                                          \
        for (int ks = 0; ks < 4; ks++) {                                           \
            uint32_t af[4][4];                                                     \
            _Pragma("unroll")                                                      \
            for (int mi = 0; mi < 4; mi++)                                         \
                ldsm4(af[mi], abase_ + swz((uint32_t)((a_row + mi * 16) * 128 +    \
                                                      (ks * 16 + a_kx) * 2)));     \
            uint32_t bf[4][2];                                                     \
            _Pragma("unroll")                                                      \
            for (int h = 0; h < 2; h++) {                                          \
                int nb = warp_n * 32 + h * 16 + b_ns;                              \
                uint32_t r[4];                                                     \
                ldsm4t(r, bbase_ + (uint32_t)(((nb >> 6) & 1) * 8192) +            \
                          swz((uint32_t)((ks * 16 + b_jr) * 128 + (nb & 63) * 2)));\
                bf[2 * h + 0][0] = r[0]; bf[2 * h + 0][1] = r[1];                  \
                bf[2 * h + 1][0] = r[2]; bf[2 * h + 1][1] = r[3];                  \
            }                                                                      \
            _Pragma("unroll")                                                      \
            for (int mi = 0; mi < 4; mi++)                                         \
                _Pragma("unroll")                                                  \
                for (int ni = 0; ni < 4; ni++)                                     \
                    mma16816(acc[mi][ni], af[mi], bf[ni]);                         \
        }                                                                          \
    } while (0)

// Direct strided epilogue (R13-proven mapping): rows RSTRIDE*r0 + rowoff
#define DIRECT_EPILOGUE(RSTRIDE, kt_, rowoff_)                                     \
    do {                                                                           \
        size_t obase = ((size_t)b << 20) + (size_t)(rowoff_) * 1024 + m0;          \
        _Pragma("unroll")                                                          \
        for (int mi = 0; mi < 4; mi++)                                             \
            _Pragma("unroll")                                                      \
            for (int ni = 0; ni < 4; ni++) {                                       \
                int r0 = (kt_) * 128 + warp_m * 64 + mi * 16 + gr;                 \
                int col = warp_n * 32 + ni * 8 + cl;                               \
                float2 v0 = { acc[mi][ni][0], acc[mi][ni][1] };                    \
                float2 v1 = { acc[mi][ni][2], acc[mi][ni][3] };                    \
                *(float2*)(out + obase + (size_t)((RSTRIDE) * r0) * 1024 + col) = v0; \
                *(float2*)(out + obase + (size_t)((RSTRIDE) * (r0 + 8)) * 1024 + col) = v1; \
                acc[mi][ni][0] = acc[mi][ni][1] = 0.0f;                            \
                acc[mi][ni][2] = acc[mi][ni][3] = 0.0f;                            \
            }                                                                      \
    } while (0)

// odd rows (2r+1): K=512, 8 chunks, smem-staged coalesced epilogue (proven)
DEV_INLINE void gemm512_body(float* __restrict__ out, int blk, uint32_t sbase, char* smem) {
    int tid = threadIdx.x;
    int lane = tid & 31, wid = tid >> 5;
    int warp_m = wid & 1;
    int warp_n = wid >> 1;

    int k0 = (blk & 3) * BM;
    int nt = blk >> 2;
    int b  = nt >> 3;
    int m0 = (nt & 7) * BN;
    const __half* Apanel = d_Codd + (size_t)k0 * 512;
    const __half* Bpanel = d_xd + (size_t)b * 512 * 1024 + m0;

    float acc[4][4][4] = {};
    int a_row = warp_m * 64 + (lane & 7) + (((lane >> 3) & 1) << 3);
    int a_kx  = (lane >> 4) << 3;
    int b_jr  = (lane & 7) + (((lane >> 3) & 1) << 3);
    int b_ns  = (lane >> 4) << 3;

    load_chunkT<512>(0, 0, tid, Apanel, Bpanel, sbase); cp_commit();
    load_chunkT<512>(64, 1, tid, Apanel, Bpanel, sbase); cp_commit();

    for (int c = 0; c < 8; c++) {
        int q = c + 2;
        if (q < 8) load_chunkT<512>(q * 64, q % 3, tid, Apanel, Bpanel, sbase);
        cp_commit();
        cp_wait<2>();
        __syncthreads();
        MMA_CHUNK(c % 3);
        __syncthreads();
    }

    float* stg = (float*)smem;
    int gr = lane >> 2, cl = (lane & 3) * 2;
#pragma unroll
    for (int mi = 0; mi < 4; mi++)
#pragma unroll
        for (int ni = 0; ni < 4; ni++) {
            int r0 = warp_m * 64 + mi * 16 + gr;
            int col = warp_n * 32 + ni * 8 + cl;
            stg[r0 * 132 + col]           = acc[mi][ni][0];
            stg[r0 * 132 + col + 1]       = acc[mi][ni][1];
            stg[(r0 + 8) * 132 + col]     = acc[mi][ni][2];
            stg[(r0 + 8) * 132 + col + 1] = acc[mi][ni][3];
        }
    __syncthreads();

    size_t ob = ((size_t)b << 20) + (size_t)(2 * k0 + 1) * 1024 + m0;
#pragma unroll
    for (int i = 0; i < 16; i++) {
        int idx = i * THREADS + tid;
        int row = idx >> 5;
        int c4 = (idx & 31) * 4;
        float4 v = *(const float4*)(stg + row * 132 + c4);
        *(float4*)(out + ob + (size_t)row * 2048 + c4) = v;
    }
}

// rows 4t+2: Ceo(256x256) @ sd, both k-tiles in one 8-chunk CTA (epilogue at c=3,7)
DEV_INLINE void gemmEO_body(float* __restrict__ out, int blk, uint32_t sbase) {
    int tid = threadIdx.x;
    int lane = tid & 31, wid = tid >> 5;
    int warp_m = wid & 1;
    int warp_n = wid >> 1;

    int b  = blk >> 3;
    int m0 = (blk & 7) * BN;
    const __half* Bp = d_xsd + (size_t)b * 256 * 1024 + m0;

    float acc[4][4][4] = {};
    int a_row = warp_m * 64 + (lane & 7) + (((lane >> 3) & 1) << 3);
    int a_kx  = (lane >> 4) << 3;
    int b_jr  = (lane & 7) + (((lane >> 3) & 1) << 3);
    int b_ns  = (lane >> 4) << 3;
    int gr = lane >> 2, cl = (lane & 3) * 2;

    load_chunkT<256>(0, 0, tid, d_Ceo, Bp, sbase); cp_commit();
    load_chunkT<256>(64, 1, tid, d_Ceo, Bp, sbase); cp_commit();

    for (int c = 0; c < 8; c++) {
        int q = c + 2;
        if (q < 8) {
            const __half* Aq = d_Ceo + (size_t)((q >> 2) * 128) * 256;
            load_chunkT<256>((q & 3) * 64, q % 3, tid, Aq, Bp, sbase);
        }
        cp_commit();
        cp_wait<2>();
        __syncthreads();
        MMA_CHUNK(c % 3);
        if (c == 3 || c == 7) DIRECT_EPILOGUE(4, c >> 2, 2);
        __syncthreads();
    }
}

// rows 8u (Cee2 @ ss2) and 8u+4 (Ceo2 @ sd2): 4-chunk CTA, epilogue at c=1,3
DEV_INLINE void gemmEE2_body(float* __restrict__ out, int blk, uint32_t sbase) {
    int tid = threadIdx.x;
    int lane = tid & 31, wid = tid >> 5;
    int warp_m = wid & 1;
    int warp_n = wid >> 1;

    int b  = blk >> 3;
    int m0 = (blk & 7) * BN;
    const __half* Bss2 = d_xss2 + (size_t)b * 128 * 1024 + m0;
    const __half* Bsd2 = d_xsd2 + (size_t)b * 128 * 1024 + m0;

    float acc[4][4][4] = {};
    int a_row = warp_m * 64 + (lane & 7) + (((lane >> 3) & 1) << 3);
    int a_kx  = (lane >> 4) << 3;
    int b_jr  = (lane & 7) + (((lane >> 3) & 1) << 3);
    int b_ns  = (lane >> 4) << 3;
    int gr = lane >> 2, cl = (lane & 3) * 2;

    load_chunkT<128>(0, 0, tid, d_Cee2, Bss2, sbase); cp_commit();
    load_chunkT<128>(64, 1, tid, d_Cee2, Bss2, sbase); cp_commit();

    for (int c = 0; c < 4; c++) {
        int q = c + 2;
        if (q < 4) load_chunkT<128>((q & 1) * 64, q % 3, tid, d_Ceo2, Bsd2, sbase);
        cp_commit();
        cp_wait<2>();
        __syncthreads();
        MMA_CHUNK(c % 3);
        if (c == 1) DIRECT_EPILOGUE(8, 0, 0);      // rows 8u
        if (c == 3) DIRECT_EPILOGUE(8, 0, 4);      // rows 8u+4
        __syncthreads();
    }
}

// One launch: [0,1024) odd | [1024,1280) eo | [1280,1536) eee+eeo (short CTAs last)
__global__ void __launch_bounds__(THREADS, 2) fused_gemm_kernel(float* __restrict__ out) {
    extern __shared__ char smem[];
    uint32_t sbase = smem_u32(smem);
    int blk = blockIdx.x;
    if (blk < 1024)      gemm512_body(out, blk, sbase, smem);
    else if (blk < 1280) gemmEO_body(out, blk - 1024, sbase);
    else                 gemmEE2_body(out, blk - 1280, sbase);
}

// ---------------------------------------------------------------- launch
extern "C" void kernel_launch(void* const* d_in, const int* in_sizes, int n_in,
                              void* d_out, int out_size) {
    (void)in_sizes; (void)n_in; (void)out_size;
    const float* x = (const float*)d_in[0];
    float* out = (float*)d_out;

    prep_kernel<<<3456, 256>>>(x);

    cudaFuncSetAttribute(fused_gemm_kernel,
                         cudaFuncAttributeMaxDynamicSharedMemorySize, SMEM_TOTAL);
    fused_gemm_kernel<<<1536, THREADS, SMEM_TOTAL>>>(out);
}